// round 15
// baseline (speedup 1.0000x reference)
#include <cuda_runtime.h>
#include <math.h>
#include <stdint.h>

#define BATCH 4
#define CH    512
#define LEN   2048

// conv outputs (tf32 bit patterns) + attention output (tf32 bits)
__device__ float g_yq[BATCH*CH*LEN];
__device__ float g_yk[BATCH*CH*LEN];
__device__ float g_yv[BATCH*CH*LEN];
__device__ float g_z [BATCH*CH*LEN];
// pre-converted tf32 inputs
__device__ float g_qt[BATCH*CH*LEN];
__device__ float g_kt[BATCH*CH*LEN];
__device__ float g_vt[BATCH*CH*LEN];
__device__ float g_wqt[CH*CH*3];
__device__ float g_wkt[CH*CH*3];
__device__ float g_wvt[CH*CH*3];
__device__ float g_wft[CH*CH*3];

// ---- tf32 / mma helpers -----------------------------------------------------
__device__ __forceinline__ uint32_t tf32_rna(float a) {
    uint32_t r; asm("cvt.rna.tf32.f32 %0, %1;" : "=r"(r) : "f"(a)); return r;
}
__device__ __forceinline__ void mma_tf32(float4& d, const uint32_t* a,
                                         uint32_t b0, uint32_t b1) {
    asm volatile(
        "mma.sync.aligned.m16n8k8.row.col.f32.tf32.tf32.f32 "
        "{%0,%1,%2,%3},{%4,%5,%6,%7},{%8,%9},{%0,%1,%2,%3};"
        : "+f"(d.x), "+f"(d.y), "+f"(d.z), "+f"(d.w)
        : "r"(a[0]), "r"(a[1]), "r"(a[2]), "r"(a[3]), "r"(b0), "r"(b1));
}

// ---- cp.async helpers ---------------------------------------------------------
__device__ __forceinline__ void cp16(void* dst, const void* src) {
    uint32_t d = (uint32_t)__cvta_generic_to_shared(dst);
    asm volatile("cp.async.cg.shared.global [%0], [%1], 16;"
                 :: "r"(d), "l"(src));
}
__device__ __forceinline__ void cp4z(void* dst, const void* src, bool valid) {
    uint32_t d = (uint32_t)__cvta_generic_to_shared(dst);
    int sz = valid ? 4 : 0;
    asm volatile("cp.async.ca.shared.global [%0], [%1], 4, %2;"
                 :: "r"(d), "l"(src), "r"(sz));
}
__device__ __forceinline__ void cp_commit() {
    asm volatile("cp.async.commit_group;");
}
template<int N> __device__ __forceinline__ void cp_wait() {
    asm volatile("cp.async.wait_group %0;" :: "n"(N));
}

// ---- prep: fp32 -> tf32 bit patterns -----------------------------------------
__global__ __launch_bounds__(256)
void cvt_big_k(const float* __restrict__ q, const float* __restrict__ k,
               const float* __restrict__ v,
               float* __restrict__ qt, float* __restrict__ kt,
               float* __restrict__ vt)
{
    const float* s = blockIdx.y == 0 ? q : (blockIdx.y == 1 ? k : v);
    float* d       = blockIdx.y == 0 ? qt : (blockIdx.y == 1 ? kt : vt);
    size_t i = ((size_t)blockIdx.x * 256 + threadIdx.x) << 2;
    float4 x = *(const float4*)(s + i);
    uint4 u = make_uint4(tf32_rna(x.x), tf32_rna(x.y),
                         tf32_rna(x.z), tf32_rna(x.w));
    *(uint4*)(d + i) = u;
}

__global__ __launch_bounds__(256)
void cvt_w_k(const float* __restrict__ w0, const float* __restrict__ w1,
             const float* __restrict__ w2, const float* __restrict__ w3,
             float* __restrict__ t0, float* __restrict__ t1,
             float* __restrict__ t2, float* __restrict__ t3)
{
    const float* s; float* d;
    if (blockIdx.y == 0)      { s = w0; d = t0; }
    else if (blockIdx.y == 1) { s = w1; d = t1; }
    else if (blockIdx.y == 2) { s = w2; d = t2; }
    else                      { s = w3; d = t3; }
    size_t i = ((size_t)blockIdx.x * 256 + threadIdx.x) << 2;
    float4 x = *(const float4*)(s + i);
    uint4 u = make_uint4(tf32_rna(x.x), tf32_rna(x.y),
                         tf32_rna(x.z), tf32_rna(x.w));
    *(uint4*)(d + i) = u;
}

// ---------------------------------------------------------------------------
// Conv1d (k=3,'same') on tensor cores, single-pass tf32 (inputs pre-converted).
// Block tile 128co x 128pos, 256 thr = 8 warps; warp tile 32co x 64pos.
// 3-stage cp.async pipeline in DYNAMIC smem (55 KB), ONE barrier per chunk.
// (R14 proven, incl. tail cp_wait<0> fix.)
// ---------------------------------------------------------------------------
#define W_SZ   (128 * 28)
#define X_SZ   (8 * 136)
#define ST_SZ  (W_SZ + X_SZ)
#define CONV_SMEM (3 * ST_SZ * 4)

template<bool OUT_TF32>
__device__ __forceinline__
void conv_body_ca(const float* __restrict__ x, const float* __restrict__ w,
                  const float* __restrict__ bias, float* __restrict__ y,
                  int b, int co0, int l0)
{
    extern __shared__ __align__(16) uint32_t dsm[];

    const int tid  = threadIdx.x;
    const int lane = tid & 31;
    const int wid  = tid >> 5;
    const int g    = lane >> 2;
    const int tg   = lane & 3;
    const int wco  = (wid & 3) << 5;
    const int wpos = (wid >> 2) << 6;
    const float* xb = x + (size_t)b * (CH * LEN);

    float4 acc[2][8];
    #pragma unroll
    for (int m = 0; m < 2; m++)
        #pragma unroll
        for (int i = 0; i < 8; i++) acc[m][i] = make_float4(0.f, 0.f, 0.f, 0.f);

    const int xrow = tid >> 5;
    const int xc4  = (tid & 31) << 2;
    const int wcoL = tid >> 1;
    const int wj   = (tid & 1) * 12;

    uint32_t* w0 = dsm;               uint32_t* x0 = dsm + W_SZ;
    uint32_t* w1 = dsm + ST_SZ;       uint32_t* x1 = dsm + ST_SZ + W_SZ;
    uint32_t* w2 = dsm + 2 * ST_SZ;   uint32_t* x2 = dsm + 2 * ST_SZ + W_SZ;

#define CSTAGE(CI, WD, XD)                                                    \
    {                                                                         \
        cp16(&(XD)[xrow * 136 + 4 + xc4],                                     \
             xb + (size_t)((CI) + xrow) * LEN + l0 + xc4);                    \
        if (tid < 16) {                                                       \
            int hr = tid & 7;                                                 \
            bool left = tid < 8;                                              \
            int hcol = left ? 3 : 132;                                        \
            int gl = left ? (l0 - 1) : (l0 + 128);                            \
            cp4z(&(XD)[hr * 136 + hcol],                                      \
                 xb + (size_t)((CI) + hr) * LEN + gl,                         \
                 gl >= 0 && gl < LEN);                                        \
        }                                                                     \
        const float* wp = w + (size_t)(co0 + wcoL) * (CH * 3) + (CI) * 3 + wj;\
        cp16(&(WD)[wcoL * 28 + wj    ], wp    );                              \
        cp16(&(WD)[wcoL * 28 + wj + 4], wp + 4);                              \
        cp16(&(WD)[wcoL * 28 + wj + 8], wp + 8);                              \
    }

#define CCOMPUTE(WD, XD)                                                      \
    _Pragma("unroll")                                                         \
    for (int t = 0; t < 3; t++) {                                             \
        uint32_t ah[2][4];                                                    \
        const int r0 = tg * 3 + t;                                            \
        _Pragma("unroll")                                                     \
        for (int m = 0; m < 2; m++) {                                         \
            const int cb = wco + (m << 4);                                    \
            ah[m][0] = (WD)[(cb + g    ) * 28 + r0     ];                     \
            ah[m][1] = (WD)[(cb + g + 8) * 28 + r0     ];                     \
            ah[m][2] = (WD)[(cb + g    ) * 28 + r0 + 12];                     \
            ah[m][3] = (WD)[(cb + g + 8) * 28 + r0 + 12];                     \
        }                                                                     \
        _Pragma("unroll")                                                     \
        for (int a2 = 0; a2 < 8; a2++) {                                      \
            const int c = wpos + (a2 << 3) + g + t + 3;                       \
            uint32_t bh0 = (XD)[ tg      * 136 + c];                          \
            uint32_t bh1 = (XD)[(tg + 4) * 136 + c];                          \
            mma_tf32(acc[0][a2], ah[0], bh0, bh1);                            \
            mma_tf32(acc[1][a2], ah[1], bh0, bh1);                            \
        }                                                                     \
    }

    CSTAGE(0, w0, x0); cp_commit();
    CSTAGE(8, w1, x1); cp_commit();

    #pragma unroll 1
    for (int it = 0; it < 64; it++) {
        if (it < 63) cp_wait<1>(); else cp_wait<0>();
        __syncthreads();
        CCOMPUTE(w0, x0);
        if (it + 2 < 64) {
            CSTAGE((it + 2) << 3, w2, x2);
            cp_commit();
        }
        uint32_t* tw = w0; w0 = w1; w1 = w2; w2 = tw;
        uint32_t* tx = x0; x0 = x1; x1 = x2; x2 = tx;
    }
#undef CSTAGE
#undef CCOMPUTE

    #pragma unroll
    for (int m = 0; m < 2; m++) {
        const int row = co0 + wco + (m << 4) + g;
        const float bv0 = bias[row], bv1 = bias[row + 8];
        float* y0 = y + ((size_t)b * CH + row) * LEN + l0 + wpos + (tg << 1);
        #pragma unroll
        for (int a2 = 0; a2 < 8; a2++) {
            float r00 = acc[m][a2].x + bv0, r01 = acc[m][a2].y + bv0;
            float r10 = acc[m][a2].z + bv1, r11 = acc[m][a2].w + bv1;
            if (OUT_TF32) {
                r00 = __uint_as_float(tf32_rna(r00));
                r01 = __uint_as_float(tf32_rna(r01));
                r10 = __uint_as_float(tf32_rna(r10));
                r11 = __uint_as_float(tf32_rna(r11));
            }
            *(float2*)(y0 + (a2 << 3)) = make_float2(r00, r01);
            *(float2*)(y0 + (size_t)8 * LEN + (a2 << 3)) = make_float2(r10, r11);
        }
    }
}

__global__ __launch_bounds__(256)
void conv_qkv_k(const float* __restrict__ qt, const float* __restrict__ kt,
                const float* __restrict__ vt,
                const float* __restrict__ wqt, const float* __restrict__ wkt,
                const float* __restrict__ wvt,
                const float* __restrict__ bq, const float* __restrict__ bk,
                const float* __restrict__ bv,
                float* __restrict__ yq, float* __restrict__ yk,
                float* __restrict__ yv)
{
    int sel = blockIdx.z >> 2, b = blockIdx.z & 3;
    const float* x; const float* w; const float* bia; float* y;
    if (sel == 0)      { x = qt; w = wqt; bia = bq; y = yq; }
    else if (sel == 1) { x = kt; w = wkt; bia = bk; y = yk; }
    else               { x = vt; w = wvt; bia = bv; y = yv; }
    conv_body_ca<true>(x, w, bia, y, b, blockIdx.y << 7, blockIdx.x << 7);
}

__global__ __launch_bounds__(256)
void conv_fc_k(const float* __restrict__ zt, const float* __restrict__ wft,
               const float* __restrict__ bias, float* __restrict__ out)
{
    conv_body_ca<false>(zt, wft, bias, out, blockIdx.z,
                        blockIdx.y << 7, blockIdx.x << 7);
}

// ---------------------------------------------------------------------------
// Flash attention, ONE barrier per j-tile:
//  - K AND V double-buffered (64 KB dynamic smem). Staging in iter j targets
//    buffers (j+1)%2, whose last readers finished in iter j-1 -> safe after
//    the single top-of-iter barrier.
//  - P fed to PV mma as raw fp32 bits (HW takes top tf32 bits; truncation,
//    same error magnitude as RNA) -> no P cvts.
//  - no online max (logits bounded), scale 2^-6 folded into Q.
// Swizzles: K col^(4*(row&7)); V col^(8*(row&3)).
// ---------------------------------------------------------------------------
#define KV_SZ     (64 * 64)            // u32 per buffer
#define ATTN_SMEM (4 * KV_SZ * 4)      // 2xK + 2xV = 65536 B

__global__ __launch_bounds__(128)
void attn_k(const float* __restrict__ yq, const float* __restrict__ yk,
            const float* __restrict__ yv, float* __restrict__ z)
{
    extern __shared__ __align__(16) uint32_t asm_[];
    uint32_t* Ks0 = asm_;
    uint32_t* Ks1 = asm_ + KV_SZ;
    uint32_t* Vs0 = asm_ + 2 * KV_SZ;
    uint32_t* Vs1 = asm_ + 3 * KV_SZ;

    const int tid  = threadIdx.x;
    const int lane = tid & 31;
    const int wid  = tid >> 5;
    const int g    = lane >> 2;
    const int tg   = lane & 3;
    const int m0   = wid << 4;

    const int b = blockIdx.z, h = blockIdx.y;
    const int t0 = blockIdx.x << 6;
    const size_t bbase = (size_t)b * (CH * LEN);
    const int hoff = h << 6;

#define AOFF(n) (bbase + (size_t)((n) >> 2) * LEN + ((n) & 3) * 512 + hoff)

    uint32_t qa[8][4];
    {
        const float* q0 = yq + AOFF(t0 + m0 + g);
        const float* q1 = yq + AOFF(t0 + m0 + g + 8);
        const float sc = 0.015625f;
        #pragma unroll
        for (int kt = 0; kt < 8; kt++) {
            qa[kt][0] = __float_as_uint(q0[tg + 8 * kt] * sc);
            qa[kt][1] = __float_as_uint(q1[tg + 8 * kt] * sc);
            qa[kt][2] = __float_as_uint(q0[tg + 4 + 8 * kt] * sc);
            qa[kt][3] = __float_as_uint(q1[tg + 4 + 8 * kt] * sc);
        }
    }

    float lrow[2] = {0.f, 0.f};
    float4 o[8];
    #pragma unroll
    for (int nt = 0; nt < 8; nt++) o[nt] = make_float4(0.f, 0.f, 0.f, 0.f);

    const int s1 = (lane & ~3) | (tg >> 1);
    const int s2 = s1 + 2;
    const bool odd = (tg & 1);
    const int ksw = g << 2;

#define STAGE_K(J, KD)                                                        \
    for (int i = tid; i < 1024; i += 128) {                                   \
        int r = i >> 4, c4 = (i & 15) << 2;                                   \
        cp16(&(KD)[(r << 6) + (c4 ^ ((r & 7) << 2))],                         \
             yk + AOFF((J) + r) + c4);                                        \
    }
#define STAGE_V(J, VD)                                                        \
    for (int i = tid; i < 1024; i += 128) {                                   \
        int r = i >> 4, c4 = (i & 15) << 2;                                   \
        cp16(&(VD)[(r << 6) + (c4 ^ ((r & 3) << 3))],                         \
             yv + AOFF((J) + r) + c4);                                        \
    }

    STAGE_K(0, Ks0);
    STAGE_V(0, Vs0);
    cp_commit();

    #pragma unroll 1
    for (int j0 = 0; j0 < LEN; j0 += 64) {
        cp_wait<0>();
        __syncthreads();           // single barrier per tile

        const int jb = (j0 >> 6) & 1;
        const uint32_t* kb = jb ? Ks1 : Ks0;
        const uint32_t* vb = jb ? Vs1 : Vs0;

        // S = Q @ K^T  (warp: 16 x 64), pre-scaled by 1/64
        float4 sA[8];
        #pragma unroll
        for (int nt = 0; nt < 8; nt++) sA[nt] = make_float4(0.f, 0.f, 0.f, 0.f);
        #pragma unroll
        for (int kt = 0; kt < 8; kt++) {
            #pragma unroll
            for (int nt = 0; nt < 8; nt++) {
                const uint32_t* kr = &kb[(nt * 8 + g) << 6];
                uint32_t b0 = kr[(tg + 8 * kt) ^ ksw];
                uint32_t b1 = kr[(tg + 4 + 8 * kt) ^ ksw];
                mma_tf32(sA[nt], qa[kt], b0, b1);
            }
        }

        // stage next tile into the other buffers (readers finished pre-barrier)
        if (j0 + 64 < LEN) {
            uint32_t* kn = jb ? Ks0 : Ks1;
            uint32_t* vn = jb ? Vs0 : Vs1;
            STAGE_K(j0 + 64, kn);
            STAGE_V(j0 + 64, vn);
            cp_commit();
        }

        // softmax (no max shift)
        #pragma unroll
        for (int nt = 0; nt < 8; nt++) {
            sA[nt].x = __expf(sA[nt].x);
            sA[nt].y = __expf(sA[nt].y);
            sA[nt].z = __expf(sA[nt].z);
            sA[nt].w = __expf(sA[nt].w);
            lrow[0] += sA[nt].x + sA[nt].y;
            lrow[1] += sA[nt].z + sA[nt].w;
        }

        // O += P @ V  (P as raw fp32 bits; shuffle repack D-frag -> A-frag)
        #pragma unroll
        for (int kt = 0; kt < 8; kt++) {
            uint32_t ux = __float_as_uint(sA[kt].x);
            uint32_t uy = __float_as_uint(sA[kt].y);
            uint32_t uz = __float_as_uint(sA[kt].z);
            uint32_t uw = __float_as_uint(sA[kt].w);
            uint32_t x1 = __shfl_sync(0xffffffffu, ux, s1);
            uint32_t y1 = __shfl_sync(0xffffffffu, uy, s1);
            uint32_t z1 = __shfl_sync(0xffffffffu, uz, s1);
            uint32_t w1 = __shfl_sync(0xffffffffu, uw, s1);
            uint32_t x2 = __shfl_sync(0xffffffffu, ux, s2);
            uint32_t y2 = __shfl_sync(0xffffffffu, uy, s2);
            uint32_t z2 = __shfl_sync(0xffffffffu, uz, s2);
            uint32_t w2 = __shfl_sync(0xffffffffu, uw, s2);
            uint32_t pa[4];
            pa[0] = odd ? y1 : x1;
            pa[1] = odd ? w1 : z1;
            pa[2] = odd ? y2 : x2;
            pa[3] = odd ? w2 : z2;
            const uint32_t* vr0 = &vb[(tg + 8 * kt) << 6];
            const uint32_t* vr1 = &vb[(tg + 4 + 8 * kt) << 6];
            const int vsw0 = (tg & 3) << 3;
            #pragma unroll
            for (int nt = 0; nt < 8; nt++) {
                uint32_t b0 = vr0[(nt * 8 + g) ^ vsw0];
                uint32_t b1 = vr1[(nt * 8 + g) ^ vsw0];
                mma_tf32(o[nt], pa, b0, b1);
            }
        }
    }
#undef STAGE_K
#undef STAGE_V

    lrow[0] += __shfl_xor_sync(0xffffffffu, lrow[0], 1);
    lrow[0] += __shfl_xor_sync(0xffffffffu, lrow[0], 2);
    lrow[1] += __shfl_xor_sync(0xffffffffu, lrow[1], 1);
    lrow[1] += __shfl_xor_sync(0xffffffffu, lrow[1], 2);
    const float inv0 = 1.f / lrow[0];
    const float inv1 = 1.f / lrow[1];

    float* z0 = z + AOFF(t0 + m0 + g)     + (tg << 1);
    float* z1 = z + AOFF(t0 + m0 + g + 8) + (tg << 1);
    #pragma unroll
    for (int nt = 0; nt < 8; nt++) {
        *(float2*)(z0 + nt * 8) = make_float2(
            __uint_as_float(tf32_rna(o[nt].x * inv0)),
            __uint_as_float(tf32_rna(o[nt].y * inv0)));
        *(float2*)(z1 + nt * 8) = make_float2(
            __uint_as_float(tf32_rna(o[nt].z * inv1)),
            __uint_as_float(tf32_rna(o[nt].w * inv1)));
    }
#undef AOFF
}

// ---------------------------------------------------------------------------
extern "C" void kernel_launch(void* const* d_in, const int* in_sizes, int n_in,
                              void* d_out, int out_size)
{
    const float* q    = (const float*)d_in[0];
    const float* k    = (const float*)d_in[1];
    const float* v    = (const float*)d_in[2];
    const float* wq_w = (const float*)d_in[3];
    const float* wq_b = (const float*)d_in[4];
    const float* wk_w = (const float*)d_in[5];
    const float* wk_b = (const float*)d_in[6];
    const float* wv_w = (const float*)d_in[7];
    const float* wv_b = (const float*)d_in[8];
    const float* fc_w = (const float*)d_in[9];
    const float* fc_b = (const float*)d_in[10];
    float* out = (float*)d_out;

    float *yq, *yk, *yv, *zb, *qt, *kt, *vt, *wqt, *wkt, *wvt, *wft;
    cudaGetSymbolAddress((void**)&yq,  g_yq);
    cudaGetSymbolAddress((void**)&yk,  g_yk);
    cudaGetSymbolAddress((void**)&yv,  g_yv);
    cudaGetSymbolAddress((void**)&zb,  g_z);
    cudaGetSymbolAddress((void**)&qt,  g_qt);
    cudaGetSymbolAddress((void**)&kt,  g_kt);
    cudaGetSymbolAddress((void**)&vt,  g_vt);
    cudaGetSymbolAddress((void**)&wqt, g_wqt);
    cudaGetSymbolAddress((void**)&wkt, g_wkt);
    cudaGetSymbolAddress((void**)&wvt, g_wvt);
    cudaGetSymbolAddress((void**)&wft, g_wft);

    cudaFuncSetAttribute(conv_qkv_k,
        cudaFuncAttributeMaxDynamicSharedMemorySize, CONV_SMEM);
    cudaFuncSetAttribute(conv_fc_k,
        cudaFuncAttributeMaxDynamicSharedMemorySize, CONV_SMEM);
    cudaFuncSetAttribute(attn_k,
        cudaFuncAttributeMaxDynamicSharedMemorySize, ATTN_SMEM);

    dim3 gb(BATCH * CH * LEN / 1024, 3);
    cvt_big_k<<<gb, 256>>>(q, k, v, qt, kt, vt);
    dim3 gw(CH * CH * 3 / 1024, 4);
    cvt_w_k<<<gw, 256>>>(wq_w, wk_w, wv_w, fc_w, wqt, wkt, wvt, wft);

    dim3 gqkv(LEN / 128, CH / 128, 3 * BATCH);
    conv_qkv_k<<<gqkv, 256, CONV_SMEM>>>(qt, kt, vt, wqt, wkt, wvt,
                                         wq_b, wk_b, wv_b, yq, yk, yv);

    dim3 agrid(LEN / 64, 8, BATCH);
    attn_k<<<agrid, 128, ATTN_SMEM>>>(yq, yk, yv, zb);

    dim3 gfc(LEN / 128, CH / 128, BATCH);
    conv_fc_k<<<gfc, 256, CONV_SMEM>>>(zb, wft, fc_b, out);
}

// round 16
// speedup vs baseline: 1.0412x; 1.0412x over previous
#include <cuda_runtime.h>
#include <math.h>
#include <stdint.h>

#define BATCH 4
#define CH    512
#define LEN   2048

// conv outputs (tf32 bit patterns) + attention output (tf32 bits)
__device__ float g_yq[BATCH*CH*LEN];
__device__ float g_yk[BATCH*CH*LEN];
__device__ float g_yv[BATCH*CH*LEN];
__device__ float g_z [BATCH*CH*LEN];
// pre-converted tf32 inputs
__device__ float g_qt[BATCH*CH*LEN];
__device__ float g_kt[BATCH*CH*LEN];
__device__ float g_vt[BATCH*CH*LEN];
__device__ float g_wqt[CH*CH*3];
__device__ float g_wkt[CH*CH*3];
__device__ float g_wvt[CH*CH*3];
__device__ float g_wft[CH*CH*3];

// ---- tf32 / mma helpers -----------------------------------------------------
__device__ __forceinline__ uint32_t tf32_rna(float a) {
    uint32_t r; asm("cvt.rna.tf32.f32 %0, %1;" : "=r"(r) : "f"(a)); return r;
}
__device__ __forceinline__ void mma_tf32(float4& d, const uint32_t* a,
                                         uint32_t b0, uint32_t b1) {
    asm volatile(
        "mma.sync.aligned.m16n8k8.row.col.f32.tf32.tf32.f32 "
        "{%0,%1,%2,%3},{%4,%5,%6,%7},{%8,%9},{%0,%1,%2,%3};"
        : "+f"(d.x), "+f"(d.y), "+f"(d.z), "+f"(d.w)
        : "r"(a[0]), "r"(a[1]), "r"(a[2]), "r"(a[3]), "r"(b0), "r"(b1));
}

// ---- cp.async helpers ---------------------------------------------------------
__device__ __forceinline__ void cp16(void* dst, const void* src) {
    uint32_t d = (uint32_t)__cvta_generic_to_shared(dst);
    asm volatile("cp.async.cg.shared.global [%0], [%1], 16;"
                 :: "r"(d), "l"(src));
}
__device__ __forceinline__ void cp4z(void* dst, const void* src, bool valid) {
    uint32_t d = (uint32_t)__cvta_generic_to_shared(dst);
    int sz = valid ? 4 : 0;
    asm volatile("cp.async.ca.shared.global [%0], [%1], 4, %2;"
                 :: "r"(d), "l"(src), "r"(sz));
}
__device__ __forceinline__ void cp_commit() {
    asm volatile("cp.async.commit_group;");
}
template<int N> __device__ __forceinline__ void cp_wait() {
    asm volatile("cp.async.wait_group %0;" :: "n"(N));
}

// ---- prep: fp32 -> tf32 bit patterns -----------------------------------------
__global__ __launch_bounds__(256)
void cvt_big_k(const float* __restrict__ q, const float* __restrict__ k,
               const float* __restrict__ v,
               float* __restrict__ qt, float* __restrict__ kt,
               float* __restrict__ vt)
{
    const float* s = blockIdx.y == 0 ? q : (blockIdx.y == 1 ? k : v);
    float* d       = blockIdx.y == 0 ? qt : (blockIdx.y == 1 ? kt : vt);
    size_t i = ((size_t)blockIdx.x * 256 + threadIdx.x) << 2;
    float4 x = *(const float4*)(s + i);
    uint4 u = make_uint4(tf32_rna(x.x), tf32_rna(x.y),
                         tf32_rna(x.z), tf32_rna(x.w));
    *(uint4*)(d + i) = u;
}

__global__ __launch_bounds__(256)
void cvt_w_k(const float* __restrict__ w0, const float* __restrict__ w1,
             const float* __restrict__ w2, const float* __restrict__ w3,
             float* __restrict__ t0, float* __restrict__ t1,
             float* __restrict__ t2, float* __restrict__ t3)
{
    const float* s; float* d;
    if (blockIdx.y == 0)      { s = w0; d = t0; }
    else if (blockIdx.y == 1) { s = w1; d = t1; }
    else if (blockIdx.y == 2) { s = w2; d = t2; }
    else                      { s = w3; d = t3; }
    size_t i = ((size_t)blockIdx.x * 256 + threadIdx.x) << 2;
    float4 x = *(const float4*)(s + i);
    uint4 u = make_uint4(tf32_rna(x.x), tf32_rna(x.y),
                         tf32_rna(x.z), tf32_rna(x.w));
    *(uint4*)(d + i) = u;
}

// ---------------------------------------------------------------------------
// Conv1d (k=3,'same') on tensor cores, single-pass tf32 (inputs pre-converted).
// Block tile 128co x 128pos, 256 thr = 8 warps; warp tile 32co x 64pos.
// 3-stage cp.async pipeline in DYNAMIC smem (55 KB), ONE barrier per chunk.
// (R14 proven, incl. tail cp_wait<0> fix.)
// ---------------------------------------------------------------------------
#define W_SZ   (128 * 28)
#define X_SZ   (8 * 136)
#define ST_SZ  (W_SZ + X_SZ)
#define CONV_SMEM (3 * ST_SZ * 4)

template<bool OUT_TF32>
__device__ __forceinline__
void conv_body_ca(const float* __restrict__ x, const float* __restrict__ w,
                  const float* __restrict__ bias, float* __restrict__ y,
                  int b, int co0, int l0)
{
    extern __shared__ __align__(16) uint32_t dsm[];

    const int tid  = threadIdx.x;
    const int lane = tid & 31;
    const int wid  = tid >> 5;
    const int g    = lane >> 2;
    const int tg   = lane & 3;
    const int wco  = (wid & 3) << 5;
    const int wpos = (wid >> 2) << 6;
    const float* xb = x + (size_t)b * (CH * LEN);

    float4 acc[2][8];
    #pragma unroll
    for (int m = 0; m < 2; m++)
        #pragma unroll
        for (int i = 0; i < 8; i++) acc[m][i] = make_float4(0.f, 0.f, 0.f, 0.f);

    const int xrow = tid >> 5;
    const int xc4  = (tid & 31) << 2;
    const int wcoL = tid >> 1;
    const int wj   = (tid & 1) * 12;

    uint32_t* w0 = dsm;               uint32_t* x0 = dsm + W_SZ;
    uint32_t* w1 = dsm + ST_SZ;       uint32_t* x1 = dsm + ST_SZ + W_SZ;
    uint32_t* w2 = dsm + 2 * ST_SZ;   uint32_t* x2 = dsm + 2 * ST_SZ + W_SZ;

#define CSTAGE(CI, WD, XD)                                                    \
    {                                                                         \
        cp16(&(XD)[xrow * 136 + 4 + xc4],                                     \
             xb + (size_t)((CI) + xrow) * LEN + l0 + xc4);                    \
        if (tid < 16) {                                                       \
            int hr = tid & 7;                                                 \
            bool left = tid < 8;                                              \
            int hcol = left ? 3 : 132;                                        \
            int gl = left ? (l0 - 1) : (l0 + 128);                            \
            cp4z(&(XD)[hr * 136 + hcol],                                      \
                 xb + (size_t)((CI) + hr) * LEN + gl,                         \
                 gl >= 0 && gl < LEN);                                        \
        }                                                                     \
        const float* wp = w + (size_t)(co0 + wcoL) * (CH * 3) + (CI) * 3 + wj;\
        cp16(&(WD)[wcoL * 28 + wj    ], wp    );                              \
        cp16(&(WD)[wcoL * 28 + wj + 4], wp + 4);                              \
        cp16(&(WD)[wcoL * 28 + wj + 8], wp + 8);                              \
    }

#define CCOMPUTE(WD, XD)                                                      \
    _Pragma("unroll")                                                         \
    for (int t = 0; t < 3; t++) {                                             \
        uint32_t ah[2][4];                                                    \
        const int r0 = tg * 3 + t;                                            \
        _Pragma("unroll")                                                     \
        for (int m = 0; m < 2; m++) {                                         \
            const int cb = wco + (m << 4);                                    \
            ah[m][0] = (WD)[(cb + g    ) * 28 + r0     ];                     \
            ah[m][1] = (WD)[(cb + g + 8) * 28 + r0     ];                     \
            ah[m][2] = (WD)[(cb + g    ) * 28 + r0 + 12];                     \
            ah[m][3] = (WD)[(cb + g + 8) * 28 + r0 + 12];                     \
        }                                                                     \
        _Pragma("unroll")                                                     \
        for (int a2 = 0; a2 < 8; a2++) {                                      \
            const int c = wpos + (a2 << 3) + g + t + 3;                       \
            uint32_t bh0 = (XD)[ tg      * 136 + c];                          \
            uint32_t bh1 = (XD)[(tg + 4) * 136 + c];                          \
            mma_tf32(acc[0][a2], ah[0], bh0, bh1);                            \
            mma_tf32(acc[1][a2], ah[1], bh0, bh1);                            \
        }                                                                     \
    }

    CSTAGE(0, w0, x0); cp_commit();
    CSTAGE(8, w1, x1); cp_commit();

    #pragma unroll 1
    for (int it = 0; it < 64; it++) {
        if (it < 63) cp_wait<1>(); else cp_wait<0>();
        __syncthreads();
        CCOMPUTE(w0, x0);
        if (it + 2 < 64) {
            CSTAGE((it + 2) << 3, w2, x2);
            cp_commit();
        }
        uint32_t* tw = w0; w0 = w1; w1 = w2; w2 = tw;
        uint32_t* tx = x0; x0 = x1; x1 = x2; x2 = tx;
    }
#undef CSTAGE
#undef CCOMPUTE

    #pragma unroll
    for (int m = 0; m < 2; m++) {
        const int row = co0 + wco + (m << 4) + g;
        const float bv0 = bias[row], bv1 = bias[row + 8];
        float* y0 = y + ((size_t)b * CH + row) * LEN + l0 + wpos + (tg << 1);
        #pragma unroll
        for (int a2 = 0; a2 < 8; a2++) {
            float r00 = acc[m][a2].x + bv0, r01 = acc[m][a2].y + bv0;
            float r10 = acc[m][a2].z + bv1, r11 = acc[m][a2].w + bv1;
            if (OUT_TF32) {
                r00 = __uint_as_float(tf32_rna(r00));
                r01 = __uint_as_float(tf32_rna(r01));
                r10 = __uint_as_float(tf32_rna(r10));
                r11 = __uint_as_float(tf32_rna(r11));
            }
            *(float2*)(y0 + (a2 << 3)) = make_float2(r00, r01);
            *(float2*)(y0 + (size_t)8 * LEN + (a2 << 3)) = make_float2(r10, r11);
        }
    }
}

__global__ __launch_bounds__(256)
void conv_qkv_k(const float* __restrict__ qt, const float* __restrict__ kt,
                const float* __restrict__ vt,
                const float* __restrict__ wqt, const float* __restrict__ wkt,
                const float* __restrict__ wvt,
                const float* __restrict__ bq, const float* __restrict__ bk,
                const float* __restrict__ bv,
                float* __restrict__ yq, float* __restrict__ yk,
                float* __restrict__ yv)
{
    int sel = blockIdx.z >> 2, b = blockIdx.z & 3;
    const float* x; const float* w; const float* bia; float* y;
    if (sel == 0)      { x = qt; w = wqt; bia = bq; y = yq; }
    else if (sel == 1) { x = kt; w = wkt; bia = bk; y = yk; }
    else               { x = vt; w = wvt; bia = bv; y = yv; }
    conv_body_ca<true>(x, w, bia, y, b, blockIdx.y << 7, blockIdx.x << 7);
}

__global__ __launch_bounds__(256)
void conv_fc_k(const float* __restrict__ zt, const float* __restrict__ wft,
               const float* __restrict__ bias, float* __restrict__ out)
{
    conv_body_ca<false>(zt, wft, bias, out, blockIdx.z,
                        blockIdx.y << 7, blockIdx.x << 7);
}

// ---------------------------------------------------------------------------
// Flash attention, ONE barrier per j-tile with COMPILE-TIME buffer offsets:
// j-loop unrolled x2 over a 64 KB dynamic smem block; K0/K1/V0/V1 live at
// fixed u32 offsets so every LDS is base+constant (no runtime pointer selects
// — the R15 regression). P uses RNA cvts (unbiased). Safety: each body's top
// cp_wait<0>+barrier retires all readers of the pair it stages into (they
// finished in the previous body).
// ---------------------------------------------------------------------------
#define KV_SZ     4096                 // u32 per 64x64 buffer
#define A_K0      0
#define A_K1      (KV_SZ)
#define A_V0      (2 * KV_SZ)
#define A_V1      (3 * KV_SZ)
#define ATTN_SMEM (4 * KV_SZ * 4)      // 65536 B

__global__ __launch_bounds__(128)
void attn_k(const float* __restrict__ yq, const float* __restrict__ yk,
            const float* __restrict__ yv, float* __restrict__ z)
{
    extern __shared__ __align__(16) uint32_t asmem[];

    const int tid  = threadIdx.x;
    const int lane = tid & 31;
    const int wid  = tid >> 5;
    const int g    = lane >> 2;
    const int tg   = lane & 3;
    const int m0   = wid << 4;

    const int b = blockIdx.z, h = blockIdx.y;
    const int t0 = blockIdx.x << 6;
    const size_t bbase = (size_t)b * (CH * LEN);
    const int hoff = h << 6;

#define AOFF(n) (bbase + (size_t)((n) >> 2) * LEN + ((n) & 3) * 512 + hoff)

    // Q fragments (tf32 bits), scale 1/64 folded in (exact exponent shift)
    uint32_t qa[8][4];
    {
        const float* q0 = yq + AOFF(t0 + m0 + g);
        const float* q1 = yq + AOFF(t0 + m0 + g + 8);
        const float sc = 0.015625f;
        #pragma unroll
        for (int kt = 0; kt < 8; kt++) {
            qa[kt][0] = __float_as_uint(q0[tg + 8 * kt] * sc);
            qa[kt][1] = __float_as_uint(q1[tg + 8 * kt] * sc);
            qa[kt][2] = __float_as_uint(q0[tg + 4 + 8 * kt] * sc);
            qa[kt][3] = __float_as_uint(q1[tg + 4 + 8 * kt] * sc);
        }
    }

    float lrow[2] = {0.f, 0.f};
    float4 o[8];
    #pragma unroll
    for (int nt = 0; nt < 8; nt++) o[nt] = make_float4(0.f, 0.f, 0.f, 0.f);

    const int s1 = (lane & ~3) | (tg >> 1);
    const int s2 = s1 + 2;
    const bool odd = (tg & 1);
    const int ksw = g << 2;

#define STAGE_K(J, KO)                                                        \
    for (int i = tid; i < 1024; i += 128) {                                   \
        int r = i >> 4, c4 = (i & 15) << 2;                                   \
        cp16(&asmem[(KO) + (r << 6) + (c4 ^ ((r & 7) << 2))],                 \
             yk + AOFF((J) + r) + c4);                                        \
    }
#define STAGE_V(J, VO)                                                        \
    for (int i = tid; i < 1024; i += 128) {                                   \
        int r = i >> 4, c4 = (i & 15) << 2;                                   \
        cp16(&asmem[(VO) + (r << 6) + (c4 ^ ((r & 3) << 3))],                 \
             yv + AOFF((J) + r) + c4);                                        \
    }

// One 64-key tile. KO/VO are compile-time offsets for this tile's buffers;
// NKO/NVO the other pair, staged with the NEXT tile's data (if in range).
#define ATTN_BODY(J, KO, VO, NJ, NKO, NVO)                                    \
    {                                                                         \
        cp_wait<0>();                                                         \
        __syncthreads();                                                      \
        float4 sA[8];                                                         \
        _Pragma("unroll")                                                     \
        for (int nt = 0; nt < 8; nt++)                                        \
            sA[nt] = make_float4(0.f, 0.f, 0.f, 0.f);                         \
        _Pragma("unroll")                                                     \
        for (int kt = 0; kt < 8; kt++) {                                      \
            _Pragma("unroll")                                                 \
            for (int nt = 0; nt < 8; nt++) {                                  \
                const uint32_t* kr = &asmem[(KO) + ((nt * 8 + g) << 6)];      \
                uint32_t b0 = kr[(tg + 8 * kt) ^ ksw];                        \
                uint32_t b1 = kr[(tg + 4 + 8 * kt) ^ ksw];                    \
                mma_tf32(sA[nt], qa[kt], b0, b1);                             \
            }                                                                 \
        }                                                                     \
        if ((NJ) < LEN) {                                                     \
            STAGE_K((NJ), (NKO));                                             \
            STAGE_V((NJ), (NVO));                                             \
            cp_commit();                                                      \
        }                                                                     \
        _Pragma("unroll")                                                     \
        for (int nt = 0; nt < 8; nt++) {                                      \
            sA[nt].x = __expf(sA[nt].x);                                      \
            sA[nt].y = __expf(sA[nt].y);                                      \
            sA[nt].z = __expf(sA[nt].z);                                      \
            sA[nt].w = __expf(sA[nt].w);                                      \
            lrow[0] += sA[nt].x + sA[nt].y;                                   \
            lrow[1] += sA[nt].z + sA[nt].w;                                   \
        }                                                                     \
        _Pragma("unroll")                                                     \
        for (int kt = 0; kt < 8; kt++) {                                      \
            uint32_t ux = tf32_rna(sA[kt].x), uy = tf32_rna(sA[kt].y);        \
            uint32_t uz = tf32_rna(sA[kt].z), uw = tf32_rna(sA[kt].w);        \
            uint32_t x1 = __shfl_sync(0xffffffffu, ux, s1);                   \
            uint32_t y1 = __shfl_sync(0xffffffffu, uy, s1);                   \
            uint32_t z1 = __shfl_sync(0xffffffffu, uz, s1);                   \
            uint32_t w1 = __shfl_sync(0xffffffffu, uw, s1);                   \
            uint32_t x2 = __shfl_sync(0xffffffffu, ux, s2);                   \
            uint32_t y2 = __shfl_sync(0xffffffffu, uy, s2);                   \
            uint32_t z2 = __shfl_sync(0xffffffffu, uz, s2);                   \
            uint32_t w2 = __shfl_sync(0xffffffffu, uw, s2);                   \
            uint32_t pa[4];                                                   \
            pa[0] = odd ? y1 : x1;                                            \
            pa[1] = odd ? w1 : z1;                                            \
            pa[2] = odd ? y2 : x2;                                            \
            pa[3] = odd ? w2 : z2;                                            \
            const uint32_t* vr0 = &asmem[(VO) + ((tg + 8 * kt) << 6)];        \
            const uint32_t* vr1 = &asmem[(VO) + ((tg + 4 + 8 * kt) << 6)];    \
            const int vsw0 = (tg & 3) << 3;                                   \
            _Pragma("unroll")                                                 \
            for (int nt = 0; nt < 8; nt++) {                                  \
                uint32_t b0 = vr0[(nt * 8 + g) ^ vsw0];                       \
                uint32_t b1 = vr1[(nt * 8 + g) ^ vsw0];                       \
                mma_tf32(o[nt], pa, b0, b1);                                  \
            }                                                                 \
        }                                                                     \
    }

    STAGE_K(0, A_K0);
    STAGE_V(0, A_V0);
    cp_commit();

    #pragma unroll 1
    for (int j0 = 0; j0 < LEN; j0 += 128) {
        ATTN_BODY(j0,      A_K0, A_V0, j0 + 64,  A_K1, A_V1);
        ATTN_BODY(j0 + 64, A_K1, A_V1, j0 + 128, A_K0, A_V0);
    }
#undef ATTN_BODY
#undef STAGE_K
#undef STAGE_V

    lrow[0] += __shfl_xor_sync(0xffffffffu, lrow[0], 1);
    lrow[0] += __shfl_xor_sync(0xffffffffu, lrow[0], 2);
    lrow[1] += __shfl_xor_sync(0xffffffffu, lrow[1], 1);
    lrow[1] += __shfl_xor_sync(0xffffffffu, lrow[1], 2);
    const float inv0 = 1.f / lrow[0];
    const float inv1 = 1.f / lrow[1];

    float* z0 = z + AOFF(t0 + m0 + g)     + (tg << 1);
    float* z1 = z + AOFF(t0 + m0 + g + 8) + (tg << 1);
    #pragma unroll
    for (int nt = 0; nt < 8; nt++) {
        *(float2*)(z0 + nt * 8) = make_float2(
            __uint_as_float(tf32_rna(o[nt].x * inv0)),
            __uint_as_float(tf32_rna(o[nt].y * inv0)));
        *(float2*)(z1 + nt * 8) = make_float2(
            __uint_as_float(tf32_rna(o[nt].z * inv1)),
            __uint_as_float(tf32_rna(o[nt].w * inv1)));
    }
#undef AOFF
}

// ---------------------------------------------------------------------------
extern "C" void kernel_launch(void* const* d_in, const int* in_sizes, int n_in,
                              void* d_out, int out_size)
{
    const float* q    = (const float*)d_in[0];
    const float* k    = (const float*)d_in[1];
    const float* v    = (const float*)d_in[2];
    const float* wq_w = (const float*)d_in[3];
    const float* wq_b = (const float*)d_in[4];
    const float* wk_w = (const float*)d_in[5];
    const float* wk_b = (const float*)d_in[6];
    const float* wv_w = (const float*)d_in[7];
    const float* wv_b = (const float*)d_in[8];
    const float* fc_w = (const float*)d_in[9];
    const float* fc_b = (const float*)d_in[10];
    float* out = (float*)d_out;

    float *yq, *yk, *yv, *zb, *qt, *kt, *vt, *wqt, *wkt, *wvt, *wft;
    cudaGetSymbolAddress((void**)&yq,  g_yq);
    cudaGetSymbolAddress((void**)&yk,  g_yk);
    cudaGetSymbolAddress((void**)&yv,  g_yv);
    cudaGetSymbolAddress((void**)&zb,  g_z);
    cudaGetSymbolAddress((void**)&qt,  g_qt);
    cudaGetSymbolAddress((void**)&kt,  g_kt);
    cudaGetSymbolAddress((void**)&vt,  g_vt);
    cudaGetSymbolAddress((void**)&wqt, g_wqt);
    cudaGetSymbolAddress((void**)&wkt, g_wkt);
    cudaGetSymbolAddress((void**)&wvt, g_wvt);
    cudaGetSymbolAddress((void**)&wft, g_wft);

    cudaFuncSetAttribute(conv_qkv_k,
        cudaFuncAttributeMaxDynamicSharedMemorySize, CONV_SMEM);
    cudaFuncSetAttribute(conv_fc_k,
        cudaFuncAttributeMaxDynamicSharedMemorySize, CONV_SMEM);
    cudaFuncSetAttribute(attn_k,
        cudaFuncAttributeMaxDynamicSharedMemorySize, ATTN_SMEM);

    dim3 gb(BATCH * CH * LEN / 1024, 3);
    cvt_big_k<<<gb, 256>>>(q, k, v, qt, kt, vt);
    dim3 gw(CH * CH * 3 / 1024, 4);
    cvt_w_k<<<gw, 256>>>(wq_w, wk_w, wv_w, fc_w, wqt, wkt, wvt, wft);

    dim3 gqkv(LEN / 128, CH / 128, 3 * BATCH);
    conv_qkv_k<<<gqkv, 256, CONV_SMEM>>>(qt, kt, vt, wqt, wkt, wvt,
                                         wq_b, wk_b, wv_b, yq, yk, yv);

    dim3 agrid(LEN / 64, 8, BATCH);
    attn_k<<<agrid, 128, ATTN_SMEM>>>(yq, yk, yv, zb);

    dim3 gfc(LEN / 128, CH / 128, BATCH);
    conv_fc_k<<<gfc, 256, CONV_SMEM>>>(zb, wft, fc_b, out);
}

// round 17
// speedup vs baseline: 1.0499x; 1.0083x over previous
#include <cuda_runtime.h>
#include <math.h>
#include <stdint.h>

#define BATCH 4
#define CH    512
#define LEN   2048

// conv outputs (tf32 bit patterns) + attention output (tf32 bits)
__device__ float g_yq[BATCH*CH*LEN];
__device__ float g_yk[BATCH*CH*LEN];
__device__ float g_yv[BATCH*CH*LEN];
__device__ float g_z [BATCH*CH*LEN];
// pre-converted tf32 inputs
__device__ float g_qt[BATCH*CH*LEN];
__device__ float g_kt[BATCH*CH*LEN];
__device__ float g_vt[BATCH*CH*LEN];
__device__ float g_wqt[CH*CH*3];
__device__ float g_wkt[CH*CH*3];
__device__ float g_wvt[CH*CH*3];
__device__ float g_wft[CH*CH*3];

// ---- tf32 / mma helpers -----------------------------------------------------
__device__ __forceinline__ uint32_t tf32_rna(float a) {
    uint32_t r; asm("cvt.rna.tf32.f32 %0, %1;" : "=r"(r) : "f"(a)); return r;
}
__device__ __forceinline__ void mma_tf32(float4& d, const uint32_t* a,
                                         uint32_t b0, uint32_t b1) {
    asm volatile(
        "mma.sync.aligned.m16n8k8.row.col.f32.tf32.tf32.f32 "
        "{%0,%1,%2,%3},{%4,%5,%6,%7},{%8,%9},{%0,%1,%2,%3};"
        : "+f"(d.x), "+f"(d.y), "+f"(d.z), "+f"(d.w)
        : "r"(a[0]), "r"(a[1]), "r"(a[2]), "r"(a[3]), "r"(b0), "r"(b1));
}

// ---- cp.async helpers ---------------------------------------------------------
__device__ __forceinline__ void cp16(void* dst, const void* src) {
    uint32_t d = (uint32_t)__cvta_generic_to_shared(dst);
    asm volatile("cp.async.cg.shared.global [%0], [%1], 16;"
                 :: "r"(d), "l"(src));
}
__device__ __forceinline__ void cp4z(void* dst, const void* src, bool valid) {
    uint32_t d = (uint32_t)__cvta_generic_to_shared(dst);
    int sz = valid ? 4 : 0;
    asm volatile("cp.async.ca.shared.global [%0], [%1], 4, %2;"
                 :: "r"(d), "l"(src), "r"(sz));
}
__device__ __forceinline__ void cp_commit() {
    asm volatile("cp.async.commit_group;");
}
template<int N> __device__ __forceinline__ void cp_wait() {
    asm volatile("cp.async.wait_group %0;" :: "n"(N));
}

// ---- prep: fp32 -> tf32 bit patterns -----------------------------------------
__global__ __launch_bounds__(256)
void cvt_big_k(const float* __restrict__ q, const float* __restrict__ k,
               const float* __restrict__ v,
               float* __restrict__ qt, float* __restrict__ kt,
               float* __restrict__ vt)
{
    const float* s = blockIdx.y == 0 ? q : (blockIdx.y == 1 ? k : v);
    float* d       = blockIdx.y == 0 ? qt : (blockIdx.y == 1 ? kt : vt);
    size_t i = ((size_t)blockIdx.x * 256 + threadIdx.x) << 2;
    float4 x = *(const float4*)(s + i);
    uint4 u = make_uint4(tf32_rna(x.x), tf32_rna(x.y),
                         tf32_rna(x.z), tf32_rna(x.w));
    *(uint4*)(d + i) = u;
}

__global__ __launch_bounds__(256)
void cvt_w_k(const float* __restrict__ w0, const float* __restrict__ w1,
             const float* __restrict__ w2, const float* __restrict__ w3,
             float* __restrict__ t0, float* __restrict__ t1,
             float* __restrict__ t2, float* __restrict__ t3)
{
    const float* s; float* d;
    if (blockIdx.y == 0)      { s = w0; d = t0; }
    else if (blockIdx.y == 1) { s = w1; d = t1; }
    else if (blockIdx.y == 2) { s = w2; d = t2; }
    else                      { s = w3; d = t3; }
    size_t i = ((size_t)blockIdx.x * 256 + threadIdx.x) << 2;
    float4 x = *(const float4*)(s + i);
    uint4 u = make_uint4(tf32_rna(x.x), tf32_rna(x.y),
                         tf32_rna(x.z), tf32_rna(x.w));
    *(uint4*)(d + i) = u;
}

// ---------------------------------------------------------------------------
// Conv1d (k=3,'same') on tensor cores, single-pass tf32 (inputs pre-converted).
// Block tile 128co x 128pos, 256 thr = 8 warps; warp tile 32co x 64pos.
// 3-stage cp.async pipeline in DYNAMIC smem (55 KB), ONE barrier per chunk.
// (R14 proven, incl. tail cp_wait<0> fix.)
// ---------------------------------------------------------------------------
#define W_SZ   (128 * 28)
#define X_SZ   (8 * 136)
#define ST_SZ  (W_SZ + X_SZ)
#define CONV_SMEM (3 * ST_SZ * 4)

template<bool OUT_TF32>
__device__ __forceinline__
void conv_body_ca(const float* __restrict__ x, const float* __restrict__ w,
                  const float* __restrict__ bias, float* __restrict__ y,
                  int b, int co0, int l0)
{
    extern __shared__ __align__(16) uint32_t dsm[];

    const int tid  = threadIdx.x;
    const int lane = tid & 31;
    const int wid  = tid >> 5;
    const int g    = lane >> 2;
    const int tg   = lane & 3;
    const int wco  = (wid & 3) << 5;
    const int wpos = (wid >> 2) << 6;
    const float* xb = x + (size_t)b * (CH * LEN);

    float4 acc[2][8];
    #pragma unroll
    for (int m = 0; m < 2; m++)
        #pragma unroll
        for (int i = 0; i < 8; i++) acc[m][i] = make_float4(0.f, 0.f, 0.f, 0.f);

    const int xrow = tid >> 5;
    const int xc4  = (tid & 31) << 2;
    const int wcoL = tid >> 1;
    const int wj   = (tid & 1) * 12;

    uint32_t* w0 = dsm;               uint32_t* x0 = dsm + W_SZ;
    uint32_t* w1 = dsm + ST_SZ;       uint32_t* x1 = dsm + ST_SZ + W_SZ;
    uint32_t* w2 = dsm + 2 * ST_SZ;   uint32_t* x2 = dsm + 2 * ST_SZ + W_SZ;

#define CSTAGE(CI, WD, XD)                                                    \
    {                                                                         \
        cp16(&(XD)[xrow * 136 + 4 + xc4],                                     \
             xb + (size_t)((CI) + xrow) * LEN + l0 + xc4);                    \
        if (tid < 16) {                                                       \
            int hr = tid & 7;                                                 \
            bool left = tid < 8;                                              \
            int hcol = left ? 3 : 132;                                        \
            int gl = left ? (l0 - 1) : (l0 + 128);                            \
            cp4z(&(XD)[hr * 136 + hcol],                                      \
                 xb + (size_t)((CI) + hr) * LEN + gl,                         \
                 gl >= 0 && gl < LEN);                                        \
        }                                                                     \
        const float* wp = w + (size_t)(co0 + wcoL) * (CH * 3) + (CI) * 3 + wj;\
        cp16(&(WD)[wcoL * 28 + wj    ], wp    );                              \
        cp16(&(WD)[wcoL * 28 + wj + 4], wp + 4);                              \
        cp16(&(WD)[wcoL * 28 + wj + 8], wp + 8);                              \
    }

#define CCOMPUTE(WD, XD)                                                      \
    _Pragma("unroll")                                                         \
    for (int t = 0; t < 3; t++) {                                             \
        uint32_t ah[2][4];                                                    \
        const int r0 = tg * 3 + t;                                            \
        _Pragma("unroll")                                                     \
        for (int m = 0; m < 2; m++) {                                         \
            const int cb = wco + (m << 4);                                    \
            ah[m][0] = (WD)[(cb + g    ) * 28 + r0     ];                     \
            ah[m][1] = (WD)[(cb + g + 8) * 28 + r0     ];                     \
            ah[m][2] = (WD)[(cb + g    ) * 28 + r0 + 12];                     \
            ah[m][3] = (WD)[(cb + g + 8) * 28 + r0 + 12];                     \
        }                                                                     \
        _Pragma("unroll")                                                     \
        for (int a2 = 0; a2 < 8; a2++) {                                      \
            const int c = wpos + (a2 << 3) + g + t + 3;                       \
            uint32_t bh0 = (XD)[ tg      * 136 + c];                          \
            uint32_t bh1 = (XD)[(tg + 4) * 136 + c];                          \
            mma_tf32(acc[0][a2], ah[0], bh0, bh1);                            \
            mma_tf32(acc[1][a2], ah[1], bh0, bh1);                            \
        }                                                                     \
    }

    CSTAGE(0, w0, x0); cp_commit();
    CSTAGE(8, w1, x1); cp_commit();

    #pragma unroll 1
    for (int it = 0; it < 64; it++) {
        if (it < 63) cp_wait<1>(); else cp_wait<0>();
        __syncthreads();
        CCOMPUTE(w0, x0);
        if (it + 2 < 64) {
            CSTAGE((it + 2) << 3, w2, x2);
            cp_commit();
        }
        uint32_t* tw = w0; w0 = w1; w1 = w2; w2 = tw;
        uint32_t* tx = x0; x0 = x1; x1 = x2; x2 = tx;
    }
#undef CSTAGE
#undef CCOMPUTE

    #pragma unroll
    for (int m = 0; m < 2; m++) {
        const int row = co0 + wco + (m << 4) + g;
        const float bv0 = bias[row], bv1 = bias[row + 8];
        float* y0 = y + ((size_t)b * CH + row) * LEN + l0 + wpos + (tg << 1);
        #pragma unroll
        for (int a2 = 0; a2 < 8; a2++) {
            float r00 = acc[m][a2].x + bv0, r01 = acc[m][a2].y + bv0;
            float r10 = acc[m][a2].z + bv1, r11 = acc[m][a2].w + bv1;
            if (OUT_TF32) {
                r00 = __uint_as_float(tf32_rna(r00));
                r01 = __uint_as_float(tf32_rna(r01));
                r10 = __uint_as_float(tf32_rna(r10));
                r11 = __uint_as_float(tf32_rna(r11));
            }
            *(float2*)(y0 + (a2 << 3)) = make_float2(r00, r01);
            *(float2*)(y0 + (size_t)8 * LEN + (a2 << 3)) = make_float2(r10, r11);
        }
    }
}

__global__ __launch_bounds__(256)
void conv_qkv_k(const float* __restrict__ qt, const float* __restrict__ kt,
                const float* __restrict__ vt,
                const float* __restrict__ wqt, const float* __restrict__ wkt,
                const float* __restrict__ wvt,
                const float* __restrict__ bq, const float* __restrict__ bk,
                const float* __restrict__ bv,
                float* __restrict__ yq, float* __restrict__ yk,
                float* __restrict__ yv)
{
    int sel = blockIdx.z >> 2, b = blockIdx.z & 3;
    const float* x; const float* w; const float* bia; float* y;
    if (sel == 0)      { x = qt; w = wqt; bia = bq; y = yq; }
    else if (sel == 1) { x = kt; w = wkt; bia = bk; y = yk; }
    else               { x = vt; w = wvt; bia = bv; y = yv; }
    conv_body_ca<true>(x, w, bia, y, b, blockIdx.y << 7, blockIdx.x << 7);
}

__global__ __launch_bounds__(256)
void conv_fc_k(const float* __restrict__ zt, const float* __restrict__ wft,
               const float* __restrict__ bias, float* __restrict__ out)
{
    conv_body_ca<false>(zt, wft, bias, out, blockIdx.z,
                        blockIdx.y << 7, blockIdx.x << 7);
}

// ---------------------------------------------------------------------------
// Flash attention — padded-pitch layouts, NO XOR swizzles:
//   K pitch 68: bank = 4g+tg+const (bijective over 32 lanes, conflict-free);
//               addr = base(g,tg) + 544*nt + 8*kt -> immediate offsets.
//   V pitch 72: bank = 8tg+g+const (conflict-free);
//               addr = base(tg,g) + 576*kt + 8*nt -> immediate offsets.
// Double-buffered K and V, 1 barrier/tile, compile-time buffer offsets
// (x2-unrolled j loop). RNA P cvts. Scale 2^-6 folded into Q.
// ---------------------------------------------------------------------------
#define KP_    68                      // K row pitch (u32)
#define VP_    72                      // V row pitch (u32)
#define KBUF   (64 * KP_)              // 4352 u32
#define VBUF   (64 * VP_)              // 4608 u32
#define A_K0   0
#define A_K1   (KBUF)
#define A_V0   (2 * KBUF)
#define A_V1   (2 * KBUF + VBUF)
#define ATTN_SMEM ((2 * KBUF + 2 * VBUF) * 4)   // 71680 B

__global__ __launch_bounds__(128)
void attn_k(const float* __restrict__ yq, const float* __restrict__ yk,
            const float* __restrict__ yv, float* __restrict__ z)
{
    extern __shared__ __align__(16) uint32_t asmem[];

    const int tid  = threadIdx.x;
    const int lane = tid & 31;
    const int wid  = tid >> 5;
    const int g    = lane >> 2;
    const int tg   = lane & 3;
    const int m0   = wid << 4;

    const int b = blockIdx.z, h = blockIdx.y;
    const int t0 = blockIdx.x << 6;
    const size_t bbase = (size_t)b * (CH * LEN);
    const int hoff = h << 6;

#define AOFF(n) (bbase + (size_t)((n) >> 2) * LEN + ((n) & 3) * 512 + hoff)

    // Q fragments (tf32 bits), scale 1/64 folded in (exact exponent shift)
    uint32_t qa[8][4];
    {
        const float* q0 = yq + AOFF(t0 + m0 + g);
        const float* q1 = yq + AOFF(t0 + m0 + g + 8);
        const float sc = 0.015625f;
        #pragma unroll
        for (int kt = 0; kt < 8; kt++) {
            qa[kt][0] = __float_as_uint(q0[tg + 8 * kt] * sc);
            qa[kt][1] = __float_as_uint(q1[tg + 8 * kt] * sc);
            qa[kt][2] = __float_as_uint(q0[tg + 4 + 8 * kt] * sc);
            qa[kt][3] = __float_as_uint(q1[tg + 4 + 8 * kt] * sc);
        }
    }

    float lrow[2] = {0.f, 0.f};
    float4 o[8];
    #pragma unroll
    for (int nt = 0; nt < 8; nt++) o[nt] = make_float4(0.f, 0.f, 0.f, 0.f);

    const int s1 = (lane & ~3) | (tg >> 1);
    const int s2 = s1 + 2;
    const bool odd = (tg & 1);
    // per-thread fragment-read bases (u32 indices, decomposed addressing)
    const int kbase = g * KP_ + tg;          // + KO + 544*nt + 8*kt (+4)
    const int vbase = tg * VP_ + g;          // + VO + 576*kt + 8*nt (+4*VP_)

#define STAGE_K(J, KO)                                                        \
    for (int i = tid; i < 1024; i += 128) {                                   \
        int r = i >> 4, c4 = (i & 15) << 2;                                   \
        cp16(&asmem[(KO) + r * KP_ + c4], yk + AOFF((J) + r) + c4);           \
    }
#define STAGE_V(J, VO)                                                        \
    for (int i = tid; i < 1024; i += 128) {                                   \
        int r = i >> 4, c4 = (i & 15) << 2;                                   \
        cp16(&asmem[(VO) + r * VP_ + c4], yv + AOFF((J) + r) + c4);           \
    }

#define ATTN_BODY(J, KO, VO, NJ, NKO, NVO)                                    \
    {                                                                         \
        cp_wait<0>();                                                         \
        __syncthreads();                                                      \
        float4 sA[8];                                                         \
        _Pragma("unroll")                                                     \
        for (int nt = 0; nt < 8; nt++)                                        \
            sA[nt] = make_float4(0.f, 0.f, 0.f, 0.f);                         \
        _Pragma("unroll")                                                     \
        for (int kt = 0; kt < 8; kt++) {                                      \
            _Pragma("unroll")                                                 \
            for (int nt = 0; nt < 8; nt++) {                                  \
                uint32_t b0 = asmem[(KO) + kbase + nt * (8 * KP_) + 8 * kt];  \
                uint32_t b1 = asmem[(KO) + kbase + nt * (8 * KP_) + 8 * kt + 4];\
                mma_tf32(sA[nt], qa[kt], b0, b1);                             \
            }                                                                 \
        }                                                                     \
        if ((NJ) < LEN) {                                                     \
            STAGE_K((NJ), (NKO));                                             \
            STAGE_V((NJ), (NVO));                                             \
            cp_commit();                                                      \
        }                                                                     \
        _Pragma("unroll")                                                     \
        for (int nt = 0; nt < 8; nt++) {                                      \
            sA[nt].x = __expf(sA[nt].x);                                      \
            sA[nt].y = __expf(sA[nt].y);                                      \
            sA[nt].z = __expf(sA[nt].z);                                      \
            sA[nt].w = __expf(sA[nt].w);                                      \
            lrow[0] += sA[nt].x + sA[nt].y;                                   \
            lrow[1] += sA[nt].z + sA[nt].w;                                   \
        }                                                                     \
        _Pragma("unroll")                                                     \
        for (int kt = 0; kt < 8; kt++) {                                      \
            uint32_t ux = tf32_rna(sA[kt].x), uy = tf32_rna(sA[kt].y);        \
            uint32_t uz = tf32_rna(sA[kt].z), uw = tf32_rna(sA[kt].w);        \
            uint32_t x1 = __shfl_sync(0xffffffffu, ux, s1);                   \
            uint32_t y1 = __shfl_sync(0xffffffffu, uy, s1);                   \
            uint32_t z1 = __shfl_sync(0xffffffffu, uz, s1);                   \
            uint32_t w1 = __shfl_sync(0xffffffffu, uw, s1);                   \
            uint32_t x2 = __shfl_sync(0xffffffffu, ux, s2);                   \
            uint32_t y2 = __shfl_sync(0xffffffffu, uy, s2);                   \
            uint32_t z2 = __shfl_sync(0xffffffffu, uz, s2);                   \
            uint32_t w2 = __shfl_sync(0xffffffffu, uw, s2);                   \
            uint32_t pa[4];                                                   \
            pa[0] = odd ? y1 : x1;                                            \
            pa[1] = odd ? w1 : z1;                                            \
            pa[2] = odd ? y2 : x2;                                            \
            pa[3] = odd ? w2 : z2;                                            \
            _Pragma("unroll")                                                 \
            for (int nt = 0; nt < 8; nt++) {                                  \
                uint32_t b0 = asmem[(VO) + vbase + kt * (8 * VP_) + 8 * nt];  \
                uint32_t b1 = asmem[(VO) + vbase + kt * (8 * VP_)             \
                                    + 4 * VP_ + 8 * nt];                      \
                mma_tf32(o[nt], pa, b0, b1);                                  \
            }                                                                 \
        }                                                                     \
    }

    STAGE_K(0, A_K0);
    STAGE_V(0, A_V0);
    cp_commit();

    #pragma unroll 1
    for (int j0 = 0; j0 < LEN; j0 += 128) {
        ATTN_BODY(j0,      A_K0, A_V0, j0 + 64,  A_K1, A_V1);
        ATTN_BODY(j0 + 64, A_K1, A_V1, j0 + 128, A_K0, A_V0);
    }
#undef ATTN_BODY
#undef STAGE_K
#undef STAGE_V

    lrow[0] += __shfl_xor_sync(0xffffffffu, lrow[0], 1);
    lrow[0] += __shfl_xor_sync(0xffffffffu, lrow[0], 2);
    lrow[1] += __shfl_xor_sync(0xffffffffu, lrow[1], 1);
    lrow[1] += __shfl_xor_sync(0xffffffffu, lrow[1], 2);
    const float inv0 = 1.f / lrow[0];
    const float inv1 = 1.f / lrow[1];

    float* z0 = z + AOFF(t0 + m0 + g)     + (tg << 1);
    float* z1 = z + AOFF(t0 + m0 + g + 8) + (tg << 1);
    #pragma unroll
    for (int nt = 0; nt < 8; nt++) {
        *(float2*)(z0 + nt * 8) = make_float2(
            __uint_as_float(tf32_rna(o[nt].x * inv0)),
            __uint_as_float(tf32_rna(o[nt].y * inv0)));
        *(float2*)(z1 + nt * 8) = make_float2(
            __uint_as_float(tf32_rna(o[nt].z * inv1)),
            __uint_as_float(tf32_rna(o[nt].w * inv1)));
    }
#undef AOFF
}

// ---------------------------------------------------------------------------
extern "C" void kernel_launch(void* const* d_in, const int* in_sizes, int n_in,
                              void* d_out, int out_size)
{
    const float* q    = (const float*)d_in[0];
    const float* k    = (const float*)d_in[1];
    const float* v    = (const float*)d_in[2];
    const float* wq_w = (const float*)d_in[3];
    const float* wq_b = (const float*)d_in[4];
    const float* wk_w = (const float*)d_in[5];
    const float* wk_b = (const float*)d_in[6];
    const float* wv_w = (const float*)d_in[7];
    const float* wv_b = (const float*)d_in[8];
    const float* fc_w = (const float*)d_in[9];
    const float* fc_b = (const float*)d_in[10];
    float* out = (float*)d_out;

    float *yq, *yk, *yv, *zb, *qt, *kt, *vt, *wqt, *wkt, *wvt, *wft;
    cudaGetSymbolAddress((void**)&yq,  g_yq);
    cudaGetSymbolAddress((void**)&yk,  g_yk);
    cudaGetSymbolAddress((void**)&yv,  g_yv);
    cudaGetSymbolAddress((void**)&zb,  g_z);
    cudaGetSymbolAddress((void**)&qt,  g_qt);
    cudaGetSymbolAddress((void**)&kt,  g_kt);
    cudaGetSymbolAddress((void**)&vt,  g_vt);
    cudaGetSymbolAddress((void**)&wqt, g_wqt);
    cudaGetSymbolAddress((void**)&wkt, g_wkt);
    cudaGetSymbolAddress((void**)&wvt, g_wvt);
    cudaGetSymbolAddress((void**)&wft, g_wft);

    cudaFuncSetAttribute(conv_qkv_k,
        cudaFuncAttributeMaxDynamicSharedMemorySize, CONV_SMEM);
    cudaFuncSetAttribute(conv_fc_k,
        cudaFuncAttributeMaxDynamicSharedMemorySize, CONV_SMEM);
    cudaFuncSetAttribute(attn_k,
        cudaFuncAttributeMaxDynamicSharedMemorySize, ATTN_SMEM);

    dim3 gb(BATCH * CH * LEN / 1024, 3);
    cvt_big_k<<<gb, 256>>>(q, k, v, qt, kt, vt);
    dim3 gw(CH * CH * 3 / 1024, 4);
    cvt_w_k<<<gw, 256>>>(wq_w, wk_w, wv_w, fc_w, wqt, wkt, wvt, wft);

    dim3 gqkv(LEN / 128, CH / 128, 3 * BATCH);
    conv_qkv_k<<<gqkv, 256, CONV_SMEM>>>(qt, kt, vt, wqt, wkt, wvt,
                                         wq_b, wk_b, wv_b, yq, yk, yv);

    dim3 agrid(LEN / 64, 8, BATCH);
    attn_k<<<agrid, 128, ATTN_SMEM>>>(yq, yk, yv, zb);

    dim3 gfc(LEN / 128, CH / 128, BATCH);
    conv_fc_k<<<gfc, 256, CONV_SMEM>>>(zb, wft, fc_b, out);
}